// round 6
// baseline (speedup 1.0000x reference)
#include <cuda_runtime.h>
#include <cstdint>

#define N_NODES 50000
#define HIDDEN  64
#define INDIM   512
#define OUTDIM  40
#define MAX_E   1000000

// Scratch (device globals)
__device__ __align__(16) float g_h[N_NODES * HIDDEN];     // X @ W1
__device__ __align__(16) float g_hs[N_NODES * HIDDEN];    // dinv[i] * h[i]
__device__ __align__(16) float g_agg[N_NODES * HIDDEN];
__device__ __align__(16) float g_dinv[N_NODES];
__device__ int g_cnt[N_NODES];
__device__ int g_row_ptr[N_NODES + 1];
__device__ int g_cursor[N_NODES];
__device__ int g_col[MAX_E];

// ---------------------------------------------------------------------------
__global__ void zero_cnt_kernel(int n) {
    int i = blockIdx.x * blockDim.x + threadIdx.x;
    if (i < n) g_cnt[i] = 0;
}

__global__ void hist_kernel(const int* __restrict__ dst, int E, int n) {
    int e = blockIdx.x * blockDim.x + threadIdx.x;
    if (e < E) {
        int d = dst[e];
        if ((unsigned)d < (unsigned)n) atomicAdd(&g_cnt[d], 1);
    }
}

// Single-block exclusive scan over g_cnt -> g_row_ptr (n up to ~64k ok)
__global__ __launch_bounds__(1024) void scan_kernel(int n) {
    __shared__ int warp_sums[32];
    __shared__ int carry_s;
    if (threadIdx.x == 0) carry_s = 0;
    __syncthreads();

    const int lane = threadIdx.x & 31;
    const int wid  = threadIdx.x >> 5;

    for (int base = 0; base < n; base += 1024) {
        int i = base + threadIdx.x;
        int v = (i < n) ? g_cnt[i] : 0;
        // inclusive warp scan
        int s = v;
        #pragma unroll
        for (int o = 1; o < 32; o <<= 1) {
            int t = __shfl_up_sync(0xffffffffu, s, o);
            if (lane >= o) s += t;
        }
        if (lane == 31) warp_sums[wid] = s;
        __syncthreads();
        if (wid == 0) {
            int ws = warp_sums[lane];
            #pragma unroll
            for (int o = 1; o < 32; o <<= 1) {
                int t = __shfl_up_sync(0xffffffffu, ws, o);
                if (lane >= o) ws += t;
            }
            warp_sums[lane] = ws;
        }
        __syncthreads();
        int carry = carry_s;
        int excl = s - v + (wid > 0 ? warp_sums[wid - 1] : 0) + carry;
        if (i < n) g_row_ptr[i] = excl;
        int block_total = warp_sums[31];
        __syncthreads();
        if (threadIdx.x == 0) carry_s = carry + block_total;
        __syncthreads();
    }
    if (threadIdx.x == 0) g_row_ptr[n] = carry_s;
}

// cursor = row_ptr copy; dinv = rsqrt(cnt + 1)
__global__ void prep_kernel(int n) {
    int i = blockIdx.x * blockDim.x + threadIdx.x;
    if (i < n) {
        g_cursor[i] = g_row_ptr[i];
        g_dinv[i] = rsqrtf((float)(g_cnt[i] + 1));
    }
}

__global__ void fill_kernel(const int* __restrict__ src,
                            const int* __restrict__ dst, int E, int n) {
    int e = blockIdx.x * blockDim.x + threadIdx.x;
    if (e < E) {
        int d = dst[e], s = src[e];
        if ((unsigned)d < (unsigned)n && (unsigned)s < (unsigned)n) {
            int pos = atomicAdd(&g_cursor[d], 1);
            g_col[pos] = s;
        }
    }
}

// ---------------------------------------------------------------------------
// GEMM1 (tensor cores, tf32): g_h[n,64] = X[n,512] @ W1[512,64]
// ---------------------------------------------------------------------------
__device__ __forceinline__ uint32_t f2tf32(float f) {
    uint32_t r;
    asm("cvt.rna.tf32.f32 %0, %1;" : "=r"(r) : "f"(f));
    return r;
}

#define XS_STRIDE 36
#define WS_STRIDE 72

__global__ __launch_bounds__(256) void gemm1_mma_kernel(
    const float* __restrict__ X, const float* __restrict__ W, int n)
{
    __shared__ uint32_t Xs[128 * XS_STRIDE];
    __shared__ uint32_t Ws[32 * WS_STRIDE];

    const int tid  = threadIdx.x;
    const int lane = tid & 31;
    const int wid  = tid >> 5;
    const int gid  = lane >> 2;
    const int tig  = lane & 3;
    const int wrow = wid * 16;
    const int row0 = blockIdx.x * 128;

    float acc[8][4] = {};

    for (int k0 = 0; k0 < INDIM; k0 += 32) {
        #pragma unroll
        for (int t = 0; t < 4; t++) {
            int s = t * 256 + tid;
            int r = s >> 3, q = s & 7;
            int rr = row0 + r; if (rr >= n) rr = n - 1;
            float4 v = *(const float4*)(X + (size_t)rr * INDIM + k0 + q * 4);
            uint32_t* p = Xs + r * XS_STRIDE + q * 4;
            p[0] = f2tf32(v.x); p[1] = f2tf32(v.y);
            p[2] = f2tf32(v.z); p[3] = f2tf32(v.w);
        }
        #pragma unroll
        for (int t = 0; t < 2; t++) {
            int s = t * 256 + tid;
            int kk = s >> 4, q = s & 15;
            float4 v = *(const float4*)(W + (size_t)(k0 + kk) * HIDDEN + q * 4);
            uint32_t* p = Ws + kk * WS_STRIDE + q * 4;
            p[0] = f2tf32(v.x); p[1] = f2tf32(v.y);
            p[2] = f2tf32(v.z); p[3] = f2tf32(v.w);
        }
        __syncthreads();

        #pragma unroll
        for (int kk = 0; kk < 32; kk += 8) {
            uint32_t a0 = Xs[(wrow + gid) * XS_STRIDE + kk + tig];
            uint32_t a1 = Xs[(wrow + gid + 8) * XS_STRIDE + kk + tig];
            uint32_t a2 = Xs[(wrow + gid) * XS_STRIDE + kk + tig + 4];
            uint32_t a3 = Xs[(wrow + gid + 8) * XS_STRIDE + kk + tig + 4];
            #pragma unroll
            for (int nb = 0; nb < 8; nb++) {
                uint32_t b0 = Ws[(kk + tig) * WS_STRIDE + nb * 8 + gid];
                uint32_t b1 = Ws[(kk + tig + 4) * WS_STRIDE + nb * 8 + gid];
                asm volatile(
                    "mma.sync.aligned.m16n8k8.row.col.f32.tf32.tf32.f32 "
                    "{%0,%1,%2,%3}, {%4,%5,%6,%7}, {%8,%9}, {%0,%1,%2,%3};"
                    : "+f"(acc[nb][0]), "+f"(acc[nb][1]),
                      "+f"(acc[nb][2]), "+f"(acc[nb][3])
                    : "r"(a0), "r"(a1), "r"(a2), "r"(a3), "r"(b0), "r"(b1));
            }
        }
        __syncthreads();
    }

    const int rA = row0 + wrow + gid;
    const int rB = rA + 8;
    #pragma unroll
    for (int nb = 0; nb < 8; nb++) {
        int col = nb * 8 + 2 * tig;
        if (rA < n)
            *(float2*)(g_h + (size_t)rA * HIDDEN + col) =
                make_float2(acc[nb][0], acc[nb][1]);
        if (rB < n)
            *(float2*)(g_h + (size_t)rB * HIDDEN + col) =
                make_float2(acc[nb][2], acc[nb][3]);
    }
}

// ---------------------------------------------------------------------------
// g_hs[i,:] = dinv[i] * h[i,:]
// ---------------------------------------------------------------------------
__global__ void hs_kernel(int n) {
    int idx = blockIdx.x * blockDim.x + threadIdx.x;
    if (idx >= n * 16) return;
    int i = idx >> 4;
    float d = g_dinv[i];
    float4 v = ((const float4*)g_h)[idx];
    ((float4*)g_hs)[idx] = make_float4(d * v.x, d * v.y, d * v.z, d * v.w);
}

// ---------------------------------------------------------------------------
// Gather-aggregate: agg[i,:] = dinv[i] * (sum_{e in row i} hs[col[e],:] + hs[i,:])
// 16 threads per node, one float4 lane each. No atomics.
// ---------------------------------------------------------------------------
__global__ __launch_bounds__(256) void gather_kernel(int n) {
    int idx = blockIdx.x * blockDim.x + threadIdx.x;
    if (idx >= n * 16) return;
    int node = idx >> 4, q = idx & 15;

    int beg = g_row_ptr[node];
    int end = g_row_ptr[node + 1];

    float4 acc0 = make_float4(0.f, 0.f, 0.f, 0.f);
    float4 acc1 = make_float4(0.f, 0.f, 0.f, 0.f);

    int e = beg;
    for (; e + 1 < end; e += 2) {
        int s0 = g_col[e], s1 = g_col[e + 1];
        float4 v0 = ((const float4*)g_hs)[s0 * 16 + q];
        float4 v1 = ((const float4*)g_hs)[s1 * 16 + q];
        acc0.x += v0.x; acc0.y += v0.y; acc0.z += v0.z; acc0.w += v0.w;
        acc1.x += v1.x; acc1.y += v1.y; acc1.z += v1.z; acc1.w += v1.w;
    }
    if (e < end) {
        int s0 = g_col[e];
        float4 v0 = ((const float4*)g_hs)[s0 * 16 + q];
        acc0.x += v0.x; acc0.y += v0.y; acc0.z += v0.z; acc0.w += v0.w;
    }

    float4 self = ((const float4*)g_hs)[node * 16 + q];
    float d = g_dinv[node];
    float4 o;
    o.x = d * (acc0.x + acc1.x + self.x);
    o.y = d * (acc0.y + acc1.y + self.y);
    o.z = d * (acc0.z + acc1.z + self.z);
    o.w = d * (acc0.w + acc1.w + self.w);
    ((float4*)g_agg)[idx] = o;
}

// ---------------------------------------------------------------------------
// GEMM2: out[n,40] = relu(agg + b1) @ Wfc^T + bfc
// ---------------------------------------------------------------------------
__global__ __launch_bounds__(240) void gemm2_kernel(
    const float* __restrict__ b1, const float* __restrict__ Wfc,
    const float* __restrict__ bfc, float* __restrict__ out, int n)
{
    __shared__ float hs[24 * 68];
    __shared__ float Wt[64 * 40];
    __shared__ float bfs[40];

    const int tx = threadIdx.x;     // 0..9
    const int ty = threadIdx.y;     // 0..23
    const int tid = ty * 10 + tx;

    for (int idx = tid; idx < 64 * 40; idx += 240) {
        int o = idx % 40, j = idx / 40;
        Wt[j * 40 + o] = Wfc[o * 64 + j];
    }
    if (tid < 40) bfs[tid] = bfc[tid];

    const int row0 = blockIdx.x * 24;
    for (int idx = tid; idx < 24 * 16; idx += 240) {
        int r = idx >> 4, q = idx & 15;
        int grow = row0 + r;
        float4 v = make_float4(0.f, 0.f, 0.f, 0.f);
        if (grow < n) {
            v = ((const float4*)g_agg)[grow * 16 + q];
            float4 bb = ((const float4*)b1)[q];
            v.x = fmaxf(v.x + bb.x, 0.f);
            v.y = fmaxf(v.y + bb.y, 0.f);
            v.z = fmaxf(v.z + bb.z, 0.f);
            v.w = fmaxf(v.w + bb.w, 0.f);
        }
        *(float4*)(hs + r * 68 + q * 4) = v;
    }
    __syncthreads();

    float4 acc = make_float4(0.f, 0.f, 0.f, 0.f);
    #pragma unroll
    for (int j = 0; j < 64; j++) {
        float h = hs[ty * 68 + j];
        float4 w = *(const float4*)(Wt + j * 40 + tx * 4);
        acc.x += h * w.x;
        acc.y += h * w.y;
        acc.z += h * w.z;
        acc.w += h * w.w;
    }

    int grow = row0 + ty;
    if (grow < n) {
        float4 bb = *(const float4*)(bfs + tx * 4);
        acc.x += bb.x; acc.y += bb.y; acc.z += bb.z; acc.w += bb.w;
        *(float4*)(out + (size_t)grow * OUTDIM + tx * 4) = acc;
    }
}

// ---------------------------------------------------------------------------
extern "C" void kernel_launch(void* const* d_in, const int* in_sizes, int n_in,
                              void* d_out, int out_size)
{
    const float* X     = (const float*)d_in[0];
    const int*   edges = (const int*)d_in[1];     // int64 downcast to int32 by harness
    const float* W1    = (const float*)d_in[2];
    const float* b1    = (const float*)d_in[3];
    const float* Wfc   = (const float*)d_in[4];
    const float* bfc   = (const float*)d_in[5];
    float* out = (float*)d_out;

    const int n = in_sizes[0] / INDIM;
    const int E = in_sizes[1] / 2;
    const int* src = edges;
    const int* dst = edges + E;

    zero_cnt_kernel<<<(n + 255) / 256, 256>>>(n);
    hist_kernel<<<(E + 255) / 256, 256>>>(dst, E, n);
    scan_kernel<<<1, 1024>>>(n);
    prep_kernel<<<(n + 255) / 256, 256>>>(n);
    fill_kernel<<<(E + 255) / 256, 256>>>(src, dst, E, n);
    gemm1_mma_kernel<<<(n + 127) / 128, 256>>>(X, W1, n);
    hs_kernel<<<(n * 16 + 255) / 256, 256>>>(n);
    gather_kernel<<<(n * 16 + 255) / 256, 256>>>(n);
    gemm2_kernel<<<(n + 23) / 24, dim3(10, 24)>>>(b1, Wfc, bfc, out, n);
}

// round 7
// speedup vs baseline: 1.1608x; 1.1608x over previous
#include <cuda_runtime.h>
#include <cstdint>

#define N_NODES 50000
#define HIDDEN  64
#define INDIM   512
#define OUTDIM  40

// Scratch (device globals)
__device__ __align__(16) float g_hs[N_NODES * HIDDEN];    // dinv[i] * h[i]
__device__ __align__(16) float g_agg[N_NODES * HIDDEN];   // aggregated messages
__device__ __align__(16) float g_deg[N_NODES];
__device__ __align__(16) float g_dinv[N_NODES];

// ---------------------------------------------------------------------------
// Degree: deg[i] = 1 (self loop) + #edges with dst==i
// ---------------------------------------------------------------------------
__global__ void init_deg_kernel(int n) {
    int i = blockIdx.x * blockDim.x + threadIdx.x;
    if (i < n) g_deg[i] = 1.0f;
}

__global__ void deg_accum_kernel(const int* __restrict__ dst, int E, int n) {
    int e = blockIdx.x * blockDim.x + threadIdx.x;
    if (e < E) {
        int d = dst[e];
        if ((unsigned)d < (unsigned)n) atomicAdd(&g_deg[d], 1.0f);
    }
}

// ---------------------------------------------------------------------------
// GEMM1 (tensor cores, tf32): h[n,64] = X[n,512] @ W1[512,64]
// Fused epilogue: d = rsqrt(deg[row]); hs = d*h; agg = d*hs; dinv[row] = d.
// 128-row block, 8 warps; warp = 16 rows x 64 cols via mma.m16n8k8.tf32.
// ---------------------------------------------------------------------------
__device__ __forceinline__ uint32_t f2tf32(float f) {
    uint32_t r;
    asm("cvt.rna.tf32.f32 %0, %1;" : "=r"(r) : "f"(f));
    return r;
}

#define XS_STRIDE 36
#define WS_STRIDE 72

__global__ __launch_bounds__(256) void gemm1_mma_kernel(
    const float* __restrict__ X, const float* __restrict__ W, int n)
{
    __shared__ uint32_t Xs[128 * XS_STRIDE];
    __shared__ uint32_t Ws[32 * WS_STRIDE];

    const int tid  = threadIdx.x;
    const int lane = tid & 31;
    const int wid  = tid >> 5;
    const int gid  = lane >> 2;
    const int tig  = lane & 3;
    const int wrow = wid * 16;
    const int row0 = blockIdx.x * 128;

    float acc[8][4] = {};

    for (int k0 = 0; k0 < INDIM; k0 += 32) {
        #pragma unroll
        for (int t = 0; t < 4; t++) {
            int s = t * 256 + tid;
            int r = s >> 3, q = s & 7;
            int rr = row0 + r; if (rr >= n) rr = n - 1;
            float4 v = *(const float4*)(X + (size_t)rr * INDIM + k0 + q * 4);
            uint32_t* p = Xs + r * XS_STRIDE + q * 4;
            p[0] = f2tf32(v.x); p[1] = f2tf32(v.y);
            p[2] = f2tf32(v.z); p[3] = f2tf32(v.w);
        }
        #pragma unroll
        for (int t = 0; t < 2; t++) {
            int s = t * 256 + tid;
            int kk = s >> 4, q = s & 15;
            float4 v = *(const float4*)(W + (size_t)(k0 + kk) * HIDDEN + q * 4);
            uint32_t* p = Ws + kk * WS_STRIDE + q * 4;
            p[0] = f2tf32(v.x); p[1] = f2tf32(v.y);
            p[2] = f2tf32(v.z); p[3] = f2tf32(v.w);
        }
        __syncthreads();

        #pragma unroll
        for (int kk = 0; kk < 32; kk += 8) {
            uint32_t a0 = Xs[(wrow + gid) * XS_STRIDE + kk + tig];
            uint32_t a1 = Xs[(wrow + gid + 8) * XS_STRIDE + kk + tig];
            uint32_t a2 = Xs[(wrow + gid) * XS_STRIDE + kk + tig + 4];
            uint32_t a3 = Xs[(wrow + gid + 8) * XS_STRIDE + kk + tig + 4];
            #pragma unroll
            for (int nb = 0; nb < 8; nb++) {
                uint32_t b0 = Ws[(kk + tig) * WS_STRIDE + nb * 8 + gid];
                uint32_t b1 = Ws[(kk + tig + 4) * WS_STRIDE + nb * 8 + gid];
                asm volatile(
                    "mma.sync.aligned.m16n8k8.row.col.f32.tf32.tf32.f32 "
                    "{%0,%1,%2,%3}, {%4,%5,%6,%7}, {%8,%9}, {%0,%1,%2,%3};"
                    : "+f"(acc[nb][0]), "+f"(acc[nb][1]),
                      "+f"(acc[nb][2]), "+f"(acc[nb][3])
                    : "r"(a0), "r"(a1), "r"(a2), "r"(a3), "r"(b0), "r"(b1));
            }
        }
        __syncthreads();
    }

    // Fused epilogue
    const int rA = row0 + wrow + gid;
    const int rB = rA + 8;
    float dA = (rA < n) ? rsqrtf(g_deg[rA]) : 0.f;
    float dB = (rB < n) ? rsqrtf(g_deg[rB]) : 0.f;
    if (tig == 0) {
        if (rA < n) g_dinv[rA] = dA;
        if (rB < n) g_dinv[rB] = dB;
    }
    #pragma unroll
    for (int nb = 0; nb < 8; nb++) {
        int col = nb * 8 + 2 * tig;
        if (rA < n) {
            float h0 = dA * acc[nb][0], h1 = dA * acc[nb][1];
            *(float2*)(g_hs  + (size_t)rA * HIDDEN + col) = make_float2(h0, h1);
            *(float2*)(g_agg + (size_t)rA * HIDDEN + col) =
                make_float2(dA * h0, dA * h1);
        }
        if (rB < n) {
            float h2 = dB * acc[nb][2], h3 = dB * acc[nb][3];
            *(float2*)(g_hs  + (size_t)rB * HIDDEN + col) = make_float2(h2, h3);
            *(float2*)(g_agg + (size_t)rB * HIDDEN + col) =
                make_float2(dB * h2, dB * h3);
        }
    }
}

// ---------------------------------------------------------------------------
// Edge scatter: agg[dst,:] += dinv[dst] * hs[src,:]
// 16 threads per edge; float4 gather, one v4 L2 reduction each.
// ---------------------------------------------------------------------------
__device__ __forceinline__ void red_add_v4(float* addr, float4 v) {
    asm volatile("red.global.add.v4.f32 [%0], {%1, %2, %3, %4};"
                 :: "l"(__cvta_generic_to_global(addr)),
                    "f"(v.x), "f"(v.y), "f"(v.z), "f"(v.w)
                 : "memory");
}

__global__ void scatter_kernel(const int* __restrict__ src,
                               const int* __restrict__ dst, int E, int n)
{
    int idx = blockIdx.x * blockDim.x + threadIdx.x;
    if (idx >= E * 16) return;
    int e = idx >> 4, q = idx & 15;
    int s = src[e];
    int d = dst[e];
    if ((unsigned)s >= (unsigned)n || (unsigned)d >= (unsigned)n) return;
    float coef = g_dinv[d];
    float4 v = ((const float4*)g_hs)[s * 16 + q];
    v.x *= coef; v.y *= coef; v.z *= coef; v.w *= coef;
    red_add_v4(g_agg + (size_t)d * HIDDEN + q * 4, v);
}

// ---------------------------------------------------------------------------
// GEMM2: out[n,40] = relu(agg + b1) @ Wfc^T + bfc
// ---------------------------------------------------------------------------
__global__ __launch_bounds__(240) void gemm2_kernel(
    const float* __restrict__ b1, const float* __restrict__ Wfc,
    const float* __restrict__ bfc, float* __restrict__ out, int n)
{
    __shared__ float hs[24 * 68];
    __shared__ float Wt[64 * 40];
    __shared__ float bfs[40];

    const int tx = threadIdx.x;     // 0..9
    const int ty = threadIdx.y;     // 0..23
    const int tid = ty * 10 + tx;

    for (int idx = tid; idx < 64 * 40; idx += 240) {
        int o = idx % 40, j = idx / 40;
        Wt[j * 40 + o] = Wfc[o * 64 + j];
    }
    if (tid < 40) bfs[tid] = bfc[tid];

    const int row0 = blockIdx.x * 24;
    for (int idx = tid; idx < 24 * 16; idx += 240) {
        int r = idx >> 4, q = idx & 15;
        int grow = row0 + r;
        float4 v = make_float4(0.f, 0.f, 0.f, 0.f);
        if (grow < n) {
            v = ((const float4*)g_agg)[grow * 16 + q];
            float4 bb = ((const float4*)b1)[q];
            v.x = fmaxf(v.x + bb.x, 0.f);
            v.y = fmaxf(v.y + bb.y, 0.f);
            v.z = fmaxf(v.z + bb.z, 0.f);
            v.w = fmaxf(v.w + bb.w, 0.f);
        }
        *(float4*)(hs + r * 68 + q * 4) = v;
    }
    __syncthreads();

    float4 acc = make_float4(0.f, 0.f, 0.f, 0.f);
    #pragma unroll
    for (int j = 0; j < 64; j++) {
        float h = hs[ty * 68 + j];
        float4 w = *(const float4*)(Wt + j * 40 + tx * 4);
        acc.x += h * w.x;
        acc.y += h * w.y;
        acc.z += h * w.z;
        acc.w += h * w.w;
    }

    int grow = row0 + ty;
    if (grow < n) {
        float4 bb = *(const float4*)(bfs + tx * 4);
        acc.x += bb.x; acc.y += bb.y; acc.z += bb.z; acc.w += bb.w;
        *(float4*)(out + (size_t)grow * OUTDIM + tx * 4) = acc;
    }
}

// ---------------------------------------------------------------------------
extern "C" void kernel_launch(void* const* d_in, const int* in_sizes, int n_in,
                              void* d_out, int out_size)
{
    const float* X     = (const float*)d_in[0];
    const int*   edges = (const int*)d_in[1];     // int64 downcast to int32 by harness
    const float* W1    = (const float*)d_in[2];
    const float* b1    = (const float*)d_in[3];
    const float* Wfc   = (const float*)d_in[4];
    const float* bfc   = (const float*)d_in[5];
    float* out = (float*)d_out;

    const int n = in_sizes[0] / INDIM;
    const int E = in_sizes[1] / 2;
    const int* src = edges;
    const int* dst = edges + E;

    init_deg_kernel<<<(n + 255) / 256, 256>>>(n);
    deg_accum_kernel<<<(E + 255) / 256, 256>>>(dst, E, n);
    gemm1_mma_kernel<<<(n + 127) / 128, 256>>>(X, W1, n);
    scatter_kernel<<<(E * 16 + 255) / 256, 256>>>(src, dst, E, n);
    gemm2_kernel<<<(n + 23) / 24, dim3(10, 24)>>>(b1, Wfc, bfc, out, n);
}